// round 16
// baseline (speedup 1.0000x reference)
#include <cuda_runtime.h>
#include <cuda_fp16.h>

#define NATOM 100000
#define MNBR  12
#define AF    64
#define BF    41
#define TWOA  128
#define NM    (NATOM*MNBR)          // 1200000
#define NMF   ((double)NM)
#define NF    ((double)NATOM)
#define EPSBN 1e-5
#define NT    (NM/96)               // 12500 tiles
#define PB    148                   // persistent GEMM blocks: 1/SM
#define NTC   (NATOM/32)            // 3125 kC tiles
#define PB_C  592                   // persistent kC blocks

// ---- dynamic smem layout (bytes) for kGemmStore ----
#define BH_STRIDE 28                             // u32 words per row (56 halves, conflict-free)
#define OFF_BRAW  0                              // float braw[3936]        = 15744
#define OFF_BH    15744                          // u32 bond_h[96*28]       = 10752
#define OFF_STAG  26496                          // u32 stag[96*65]         = 24960
#define OFF_IDX   51456                          // int idxS[3][96]         = 1152
#define SMEM_BYTES 52608
#define OFF_RED   OFF_STAG                       // stats reduce overlays stag

typedef unsigned long long ull;
typedef unsigned int u32;

// ---------------- scratch (device globals; no allocations) ----------------
__device__ float  d_SW[(size_t)NATOM*TWOA];      // atom @ W[0:64] + bias
__device__ float  d_PW[(size_t)NATOM*TWOA];      // atom @ W[64:128] (fp32)
__device__ u32    d_PWf[(size_t)NATOM*64];       // half2 PW pairs: [atom][j]={PW[2j],PW[2j+1]}
__device__ ull    d_gated16[(size_t)NM*32];      // fp16 gated: [row][l]={f2l,f2l+1,c2l,c2l+1}
__device__ float  d_summed[(size_t)NATOM*AF];
__device__ double d_s1[TWOA], d_q1[TWOA];
__device__ double d_s2[AF],   d_q2[AF];
__device__ float  d_g1[TWOA], d_h1[TWOA];
__device__ float  d_g2[AF],   d_h2[AF];
__device__ unsigned d_c1, d_c2;

// ---------------- helpers ----------------
__device__ __forceinline__ void ffma2(ull &d, ull a, ull b) {
    asm("fma.rn.f32x2 %0, %1, %2, %0;" : "+l"(d) : "l"(a), "l"(b));
}
__device__ __forceinline__ ull packdup(float x) {
    ull r; asm("mov.b64 %0, {%1, %1};" : "=l"(r) : "f"(x)); return r;
}
__device__ __forceinline__ float2 unpk(ull v) {
    float2 r; asm("mov.b64 {%0, %1}, %2;" : "=f"(r.x), "=f"(r.y) : "l"(v)); return r;
}
__device__ __forceinline__ float sigmoidf_(float x) {
    return __fdividef(1.0f, 1.0f + __expf(-x));
}
__device__ __forceinline__ float softplusf_(float x) {
    float e = __expf(-fabsf(x));
    return fmaxf(x, 0.0f) + __logf(1.0f + e);
}
__device__ __forceinline__ void cpasync16(void* dst_smem, const void* src) {
    unsigned s = (unsigned)__cvta_generic_to_shared(dst_smem);
    asm volatile("cp.async.cg.shared.global [%0], [%1], 16;" :: "r"(s), "l"(src) : "memory");
}
#define CP_COMMIT() asm volatile("cp.async.commit_group;" ::: "memory")
#define CP_WAIT(n)  asm volatile("cp.async.wait_group %0;" :: "n"(n) : "memory")

__device__ __forceinline__ u32 packh2(float a, float b) {
    __half2 h = __floats2half2_rn(a, b);
    return *(u32*)&h;
}
#define MMA_F16(d, a0, a1, a2, a3, b0, b1) \
    asm volatile("mma.sync.aligned.m16n8k16.row.col.f32.f16.f16.f32 " \
        "{%0,%1,%2,%3}, {%4,%5,%6,%7}, {%8,%9}, {%0,%1,%2,%3};" \
        : "+f"(d[0]), "+f"(d[1]), "+f"(d[2]), "+f"(d[3]) \
        : "r"(a0), "r"(a1), "r"(a2), "r"(a3), "r"(b0), "r"(b1))

// ---------------- kInit ----------------
__global__ void kInit() {
    int t = threadIdx.x;
    if (t < TWOA) { d_s1[t] = 0.0; d_q1[t] = 0.0; }
    if (t < AF)   { d_s2[t] = 0.0; d_q2[t] = 0.0; }
    if (t == 0)   { d_c1 = 0u; d_c2 = 0u; }
}

// ---------------- kA: SW = atom@W1 + b, PW = atom@W2 ----------------
__global__ void __launch_bounds__(256) kA(const float* __restrict__ atom,
                                          const float* __restrict__ W,
                                          const float* __restrict__ bias) {
    __shared__ __align__(16) float at[64][132];
    int t = threadIdx.x;
    int aBase = blockIdx.x * 128;
    int aCount = NATOM - aBase; if (aCount > 128) aCount = 128;

    float wreg[64];
    const float* wp = (t < 128) ? (W + t) : (W + 64 * TWOA + (t - 128));
    #pragma unroll
    for (int k = 0; k < 64; k++) wreg[k] = wp[k * TWOA];
    float bj = (t < 128) ? bias[t] : 0.0f;

    for (int idx = t; idx < 128 * 64; idx += 256) {
        int a = idx >> 6, k = idx & 63;
        at[k][a] = (a < aCount) ? atom[(size_t)(aBase + a) * AF + k] : 0.0f;
    }
    __syncthreads();

    float* dst = (t < 128) ? d_SW : d_PW;
    int j = t & 127;

    for (int c = 0; c < 16; c++) {
        int a0 = c * 8;
        ull acc[4] = {0ull, 0ull, 0ull, 0ull};
        #pragma unroll
        for (int k = 0; k < 64; k++) {
            ull wk = packdup(wreg[k]);
            const ull* ap = (const ull*)&at[k][a0];
            ffma2(acc[0], ap[0], wk);
            ffma2(acc[1], ap[1], wk);
            ffma2(acc[2], ap[2], wk);
            ffma2(acc[3], ap[3], wk);
        }
        #pragma unroll
        for (int q = 0; q < 4; q++) {
            float2 v = unpk(acc[q]);
            int a = a0 + 2 * q;
            if (a < aCount)     dst[(size_t)(aBase + a)     * TWOA + j] = v.x + bj;
            if (a + 1 < aCount) dst[(size_t)(aBase + a + 1) * TWOA + j] = v.y + bj;
        }
    }
}

// ---------------- kPack: d_PW -> half2 pair table d_PWf ----------------
__global__ void __launch_bounds__(256) kPack() {
    int id = blockIdx.x * 256 + threadIdx.x;     // NATOM*64 total
    int a = id >> 6, j = id & 63;
    float2 v = *(const float2*)(d_PW + (size_t)a * TWOA + 2 * j);
    d_PWf[id] = packh2(v.x, v.y);
}

// ============ kGemmStore: persistent fp16 mma.m16n8k16; weights in registers ============
// 768 thr = 24 warps. warp w: rowTile rt=w%6 (rows 16rt..+15), colEighth cE=w/6 (cols 32cE..+31).
// A = bond rows (fp16, no transpose, stride 28 words). B = W3 frags held in 24 regs per lane.
__global__ void __launch_bounds__(768, 1) kGemmStore(const float* __restrict__ bond,
                                                     const int*   __restrict__ nidx,
                                                     const float* __restrict__ W,
                                                     const float* __restrict__ sc,
                                                     const float* __restrict__ of) {
    extern __shared__ __align__(16) char sm[];
    float* braw   = (float*)(sm + OFF_BRAW);
    u32*   bond_h = (u32*)  (sm + OFF_BH);
    u32*   stag   = (u32*)  (sm + OFF_STAG);
    int*   idxS   = (int*)  (sm + OFF_IDX);
    __shared__ int sLast;

    int t = threadIdx.x, lane = t & 31, w = t >> 5;
    int rt = w % 6, cE = w / 6;
    int g = lane >> 2, m = lane & 3;             // m == t4
    int row0 = 16 * rt + g, row1 = row0 + 8;
    int aL0 = row0 / 12, aL1 = row1 / 12;
    int colBase = 32 * cE + 2 * m;               // + 8nn
    int lBase = 16 * (cE & 1) + m;               // + 4nn
    int isC = (cE >= 2) ? 1 : 0;

    // ---- B-fragments (weights) once into registers ----
    u32 wb[3][4][2];
    {
        const float* w3 = W + TWOA * TWOA;
        #pragma unroll
        for (int ks = 0; ks < 3; ks++)
            #pragma unroll
            for (int nn = 0; nn < 4; nn++) {
                int n = 32 * cE + 8 * nn + g;
                int kb = 16 * ks + 2 * m;
                float v0 = (kb     < BF) ? __ldg(w3 + kb * TWOA + n)       : 0.0f;
                float v1 = (kb + 1 < BF) ? __ldg(w3 + (kb + 1) * TWOA + n) : 0.0f;
                float v2 = (kb + 8 < BF) ? __ldg(w3 + (kb + 8) * TWOA + n) : 0.0f;
                float v3 = (kb + 9 < BF) ? __ldg(w3 + (kb + 9) * TWOA + n) : 0.0f;
                wb[ks][nn][0] = packh2(v0, v1);
                wb[ks][nn][1] = packh2(v2, v3);
            }
    }

    // ---- prolog: bond tile 0 + idx slots 0,1 ----
    {
        int t0 = blockIdx.x;
        const float* bsrc = bond + (size_t)t0 * 96 * BF;
        #pragma unroll
        for (int i = 0; i < 2; i++) {
            int c = t + 768 * i;
            if (c < 96 * BF / 4) cpasync16(braw + c * 4, bsrc + c * 4);
        }
        if (t < 24) {
            cpasync16(idxS + t * 4,      nidx + t0 * 96 + t * 4);
            cpasync16(idxS + 96 + t * 4, nidx + (t0 + PB) * 96 + t * 4);
        }
        CP_COMMIT();
    }

    float ls0[4] = {0, 0, 0, 0}, ls1[4] = {0, 0, 0, 0};
    float lq0[4] = {0, 0, 0, 0}, lq1[4] = {0, 0, 0, 0};

    int n = 0;
    for (int tile = blockIdx.x; tile < NT; tile += PB, ++n) {
        CP_WAIT(0);
        __syncthreads();

        // cvt braw[r][k] -> bond_h[r][wp] half2 pairs (k, k+1), zero-padded k>=41
        #pragma unroll
        for (int i = 0; i < 4; i++) {
            int id = t + 768 * i;
            if (id < 96 * BH_STRIDE) {
                int r = id / BH_STRIDE, wp = id - r * BH_STRIDE;
                int k0 = 2 * wp;
                float v0 = (k0     < BF) ? braw[r * BF + k0]     : 0.0f;
                float v1 = (k0 + 1 < BF) ? braw[r * BF + k0 + 1] : 0.0f;
                bond_h[r * BH_STRIDE + wp] = packh2(v0, v1);
            }
        }
        __syncthreads();     // braw free; bond_h ready

        // prefetch next bond tile + idx(n+2)
        {
            int nt = tile + PB;
            if (nt < NT) {
                const float* bsrc = bond + (size_t)nt * 96 * BF;
                #pragma unroll
                for (int i = 0; i < 2; i++) {
                    int c = t + 768 * i;
                    if (c < 96 * BF / 4) cpasync16(braw + c * 4, bsrc + c * 4);
                }
                int nt2 = nt + PB;
                if (nt2 < NT && t < 24)
                    cpasync16(idxS + ((n + 2) % 3) * 96 + t * 4, nidx + nt2 * 96 + t * 4);
            }
            CP_COMMIT();
        }

        // ---- fp16 MMA: 3 k-steps x 4 n-tiles; A from bond_h, B from regs ----
        float acc[4][4];
        #pragma unroll
        for (int nn = 0; nn < 4; nn++)
            #pragma unroll
            for (int u = 0; u < 4; u++) acc[nn][u] = 0.0f;

        #pragma unroll
        for (int ks = 0; ks < 3; ks++) {
            u32 a0 = bond_h[row0 * BH_STRIDE + 8 * ks + m];
            u32 a1 = bond_h[row1 * BH_STRIDE + 8 * ks + m];
            u32 a2 = bond_h[row0 * BH_STRIDE + 8 * ks + 4 + m];
            u32 a3 = bond_h[row1 * BH_STRIDE + 8 * ks + 4 + m];
            #pragma unroll
            for (int nn = 0; nn < 4; nn++)
                MMA_F16(acc[nn], a0, a1, a2, a3, wb[ks][nn][0], wb[ks][nn][1]);
        }

        // ---- epilogue (identical to validated R15) ----
        const int* idB = idxS + (n % 3) * 96;
        int i0 = idB[row0], i1 = idB[row1];
        size_t atom0 = (size_t)(tile * 8 + aL0), atom1 = (size_t)(tile * 8 + aL1);

        #pragma unroll
        for (int nn = 0; nn < 4; nn++) {
            int col = colBase + 8 * nn;          // global col, even
            float2 sw0 = __ldg((const float2*)(d_SW + atom0 * TWOA + col));
            float2 sw1 = __ldg((const float2*)(d_SW + atom1 * TWOA + col));
            u32 p0 = __ldg(d_PWf + (size_t)i0 * 64 + (col >> 1));
            u32 p1 = __ldg(d_PWf + (size_t)i1 * 64 + (col >> 1));
            float2 pw0 = __half22float2(*(__half2*)&p0);
            float2 pw1 = __half22float2(*(__half2*)&p1);
            float v00 = acc[nn][0] + sw0.x + pw0.x;
            float v01 = acc[nn][1] + sw0.y + pw0.y;
            float v10 = acc[nn][2] + sw1.x + pw1.x;
            float v11 = acc[nn][3] + sw1.y + pw1.y;
            ls0[nn] += v00 + v10;  lq0[nn] += v00 * v00 + v10 * v10;
            ls1[nn] += v01 + v11;  lq1[nn] += v01 * v01 + v11 * v11;
            int si = 2 * (lBase + 4 * nn) + isC;
            stag[row0 * 65 + si] = packh2(v00, v01);
            stag[row1 * 65 + si] = packh2(v10, v11);
        }
        __syncthreads();

        // coalesced gated store: ull[j] = {stag[r][2l], stag[r][2l+1]}
        ull* gb = d_gated16 + (size_t)tile * 96 * 32;
        #pragma unroll
        for (int i = 0; i < 4; i++) {
            int j = t + 768 * i;                 // 0..3071
            int r = j >> 5, l = j & 31;
            u32 lo = stag[r * 65 + 2 * l];
            u32 hi = stag[r * 65 + 2 * l + 1];
            __stcs(gb + j, (ull)lo | ((ull)hi << 32));
        }
    }

    // ---- stats: warp shfl-reduce then block reduce (overlay stag) ----
    __syncthreads();
    #pragma unroll
    for (int nn = 0; nn < 4; nn++) {
        #pragma unroll
        for (int s = 4; s <= 16; s <<= 1) {
            ls0[nn] += __shfl_xor_sync(0xffffffffu, ls0[nn], s);
            ls1[nn] += __shfl_xor_sync(0xffffffffu, ls1[nn], s);
            lq0[nn] += __shfl_xor_sync(0xffffffffu, lq0[nn], s);
            lq1[nn] += __shfl_xor_sync(0xffffffffu, lq1[nn], s);
        }
    }
    float* redS = (float*)(sm + OFF_RED);
    float* redQ = redS + 24 * 32;
    if (g == 0) {
        #pragma unroll
        for (int nn = 0; nn < 4; nn++) {
            int lc = 8 * nn + 2 * m;
            redS[w * 32 + lc] = ls0[nn];      redS[w * 32 + lc + 1] = ls1[nn];
            redQ[w * 32 + lc] = lq0[nn];      redQ[w * 32 + lc + 1] = lq1[nn];
        }
    }
    __syncthreads();
    if (t < TWOA) {
        int cEi = t >> 5, lc = t & 31;
        float s = 0.0f, q = 0.0f;
        #pragma unroll
        for (int r = 0; r < 6; r++) {
            s += redS[(cEi * 6 + r) * 32 + lc];
            q += redQ[(cEi * 6 + r) * 32 + lc];
        }
        atomicAdd(&d_s1[t], (double)s);
        atomicAdd(&d_q1[t], (double)q);
    }
    __syncthreads();
    if (t == 0) {
        __threadfence();
        unsigned old = atomicAdd(&d_c1, 1u);
        sLast = (old == PB - 1) ? 1 : 0;
    }
    __syncthreads();
    if (sLast && t < TWOA) {
        double s = *((volatile double*)&d_s1[t]);
        double q = *((volatile double*)&d_q1[t]);
        double mean = s / NMF;
        double var  = q / NMF - mean * mean;
        float gg = sc[t] * (float)(1.0 / sqrt(var + EPSBN));
        d_g1[t] = gg;
        d_h1[t] = of[t] - (float)mean * gg;
    }
}

// ---------------- kC: persistent; batched loads (MLP=6) per atom; BN2 stats in regs ----------
__global__ void __launch_bounds__(256) kC(const float* __restrict__ sc,
                                          const float* __restrict__ of) {
    __shared__ float rs[8][AF];
    __shared__ float rq[8][AF];
    __shared__ int sLast;
    int t = threadIdx.x;
    int lane = t & 31, w = t >> 5;
    int half = lane >> 4, q = lane & 15;
    int c0 = 4 * q;

    float4 G1A = *(const float4*)&d_g1[c0];
    float4 H1A = *(const float4*)&d_h1[c0];
    float4 G1B = *(const float4*)&d_g1[64 + c0];
    float4 H1B = *(const float4*)&d_h1[64 + c0];

    float as0 = 0, as1 = 0, as2 = 0, as3 = 0;
    float aq0 = 0, aq1 = 0, aq2 = 0, aq3 = 0;

    for (int tb = blockIdx.x; tb < NTC; tb += PB_C) {
        int aBase = tb * 32 + w * 4;
        #pragma unroll
        for (int u = 0; u < 4; u++) {
            int a = aBase + u;
            const uint4* gp = (const uint4*)(d_gated16 + (size_t)a * MNBR * 32);
            uint4 v[6];
            #pragma unroll
            for (int i = 0; i < 6; i++)
                v[i] = __ldcs(gp + (2 * i + half) * 16 + q);
            float s0 = 0.0f, s1 = 0.0f, s2 = 0.0f, s3 = 0.0f;
            #pragma unroll
            for (int i = 0; i < 6; i++) {
                float2 f01 = __half22float2(*(__half2*)&v[i].x);
                float2 c01 = __half22float2(*(__half2*)&v[i].y);
                float2 f23 = __half22float2(*(__half2*)&v[i].z);
                float2 c23 = __half22float2(*(__half2*)&v[i].w);
                float xf0 = f01.x * G1A.x + H1A.x;
                float xf1 = f01.y * G1A.y + H1A.y;
                float xf2 = f23.x * G1A.z + H1A.z;
                float xf3 = f23.y * G1A.w + H1A.w;
                float xc0 = c01.x * G1B.x + H1B.x;
                float xc1 = c01.y * G1B.y + H1B.y;
                float xc2 = c23.x * G1B.z + H1B.z;
                float xc3 = c23.y * G1B.w + H1B.w;
                s0 += sigmoidf_(xf0) * softplusf_(xc0);
                s1 += sigmoidf_(xf1) * softplusf_(xc1);
                s2 += sigmoidf_(xf2) * softplusf_(xc2);
                s3 += sigmoidf_(xf3) * softplusf_(xc3);
            }
            s0 += __shfl_xor_sync(0xffffffffu, s0, 16);
            s1 += __shfl_xor_sync(0xffffffffu, s1, 16);
            s2 += __shfl_xor_sync(0xffffffffu, s2, 16);
            s3 += __shfl_xor_sync(0xffffffffu, s3, 16);
            if (half == 0) {
                float4 sv; sv.x = s0; sv.y = s1; sv.z = s2; sv.w = s3;
                *(float4*)&d_summed[(size_t)a * AF + c0] = sv;
                as0 += s0; aq0 += s0 * s0;
                as1 += s1; aq1 += s1 * s1;
                as2 += s2; aq2 += s2 * s2;
                as3 += s3; aq3 += s3 * s3;
            }
        }
    }

    if (half == 0) {
        float4 sv; sv.x = as0; sv.y = as1; sv.z = as2; sv.w = as3;
        *(float4*)&rs[w][c0] = sv;
        float4 qv; qv.x = aq0; qv.y = aq1; qv.z = aq2; qv.w = aq3;
        *(float4*)&rq[w][c0] = qv;
    }
    __syncthreads();
    if (t < AF) {
        float s = 0.0f, qq = 0.0f;
        #pragma unroll
        for (int r = 0; r < 8; r++) { s += rs[r][t]; qq += rq[r][t]; }
        atomicAdd(&d_s2[t], (double)s);
        atomicAdd(&d_q2[t], (double)qq);
    }
    __syncthreads();
    if (t == 0) {
        __threadfence();
        unsigned old = atomicAdd(&d_c2, 1u);
        sLast = (old == PB_C - 1) ? 1 : 0;
    }
    __syncthreads();
    if (sLast && t < AF) {
        double s = *((volatile double*)&d_s2[t]);
        double qq = *((volatile double*)&d_q2[t]);
        double mean = s / NF;
        double var  = qq / NF - mean * mean;
        float g = sc[t] * (float)(1.0 / sqrt(var + EPSBN));
        d_g2[t] = g;
        d_h2[t] = of[t] - (float)mean * g;
    }
}

// ---------------- kD: out = softplus(atom + BN2(summed)) ----------------
__global__ void __launch_bounds__(256) kD(const float* __restrict__ atom,
                                          float* __restrict__ out) {
    int i = blockIdx.x * 256 + threadIdx.x;
    int c = i & (AF - 1);
    float y = d_summed[i] * d_g2[c] + d_h2[c];
    out[i] = softplusf_(atom[i] + y);
}

// ---------------- launch ----------------
extern "C" void kernel_launch(void* const* d_in, const int* in_sizes, int n_in,
                              void* d_out, int out_size) {
    const int*   nidx = (const int*)  d_in[0];
    const float* atom = (const float*)d_in[1];
    const float* bond = (const float*)d_in[2];
    const float* W    = (const float*)d_in[3];
    const float* bias = (const float*)d_in[4];
    const float* bn1s = (const float*)d_in[5];
    const float* bn1o = (const float*)d_in[6];
    const float* bn2s = (const float*)d_in[7];
    const float* bn2o = (const float*)d_in[8];
    float* out = (float*)d_out;

    cudaFuncSetAttribute(kGemmStore, cudaFuncAttributeMaxDynamicSharedMemorySize, SMEM_BYTES);

    kInit<<<1, 128>>>();                                                     // slot 1
    kA<<<(NATOM + 127) / 128, 256>>>(atom, W, bias);                         // slot 2
    kPack<<<(NATOM * 64) / 256, 256>>>();                                    // slot 3
    kGemmStore<<<PB, 768, SMEM_BYTES>>>(bond, nidx, W, bn1s, bn1o);          // slot 4 (ncu)
    kC<<<PB_C, 256>>>(bn2s, bn2o);                                           // slot 5
    kD<<<(NATOM * AF) / 256, 256>>>(atom, out);                              // slot 6
}

// round 17
// speedup vs baseline: 1.1541x; 1.1541x over previous
#include <cuda_runtime.h>
#include <cuda_fp16.h>

#define NATOM 100000
#define MNBR  12
#define AF    64
#define BF    41
#define TWOA  128
#define NM    (NATOM*MNBR)          // 1200000
#define NMF   ((double)NM)
#define NF    ((double)NATOM)
#define EPSBN 1e-5
#define NT    (NM/96)               // 12500 tiles
#define PBLOCKS 296                 // persistent GEMM: 2 blocks/SM x 148 SMs
#define NTC    (NATOM/32)           // 3125 kC tiles
#define PB_C   444                  // persistent kC: 3 blocks/SM x 148 SMs

// ---- dynamic smem layout (bytes) for persistent kGemmStore (R13 proven) ----
#define BT_PAD    104
#define OFF_WS    0                              // float Ws[41*128]        = 20992
#define OFF_BT    20992                          // float bT[41*104]        = 17056
#define OFF_BRAW  38048                          // float braw[3936]        = 15744 (single buf)
#define OFF_SWS   53792                          // float SWs[2][1024]      = 8192
#define OFF_PWS   61984                          // ull   PWs[2][96*32]     = 49152
#define OFF_IDX   111136                         // int   idxS[3][96]       = 1152
#define SMEM_BYTES 112288                        // x2 blocks = 224.6 KB (<= 228 KB)
#define OFF_RED   OFF_BRAW                       // red 12*128*2*4 = 12288 <= 15744 (overlay)

typedef unsigned long long ull;
typedef unsigned int u32;

// ---------------- scratch (device globals; no allocations) ----------------
__device__ float  d_SW[(size_t)NATOM*TWOA];      // atom @ W[0:64] + bias
__device__ ull    d_PW16[(size_t)NATOM*32];      // packed fp16 PW: ull l = {2l,2l+1,64+2l,64+2l+1}
__device__ ull    d_gated16[(size_t)NM*32];      // fp16 gated, same packing (307 MB)
__device__ float  d_summed[(size_t)NATOM*AF];
__device__ double d_s1[TWOA], d_q1[TWOA];
__device__ double d_s2[AF],   d_q2[AF];
__device__ float  d_g1[TWOA], d_h1[TWOA];
__device__ float  d_g2[AF],   d_h2[AF];
__device__ unsigned d_c1, d_c2;

// ---------------- helpers ----------------
__device__ __forceinline__ void ffma2(ull &d, ull a, ull b) {
    asm("fma.rn.f32x2 %0, %1, %2, %0;" : "+l"(d) : "l"(a), "l"(b));
}
__device__ __forceinline__ ull packdup(float x) {
    ull r; asm("mov.b64 %0, {%1, %1};" : "=l"(r) : "f"(x)); return r;
}
__device__ __forceinline__ float2 unpk(ull v) {
    float2 r; asm("mov.b64 {%0, %1}, %2;" : "=f"(r.x), "=f"(r.y) : "l"(v)); return r;
}
__device__ __forceinline__ float sigmoidf_(float x) {
    return __fdividef(1.0f, 1.0f + __expf(-x));
}
__device__ __forceinline__ float softplusf_(float x) {
    float e = __expf(-fabsf(x));
    return fmaxf(x, 0.0f) + __logf(1.0f + e);
}
__device__ __forceinline__ void cpasync16(void* dst_smem, const void* src) {
    unsigned s = (unsigned)__cvta_generic_to_shared(dst_smem);
    asm volatile("cp.async.cg.shared.global [%0], [%1], 16;" :: "r"(s), "l"(src) : "memory");
}
#define CP_COMMIT() asm volatile("cp.async.commit_group;" ::: "memory")
#define CP_WAIT(n)  asm volatile("cp.async.wait_group %0;" :: "n"(n) : "memory")
__device__ __forceinline__ u32 packh2(float a, float b) {
    __half2 h = __floats2half2_rn(a, b);
    return *(u32*)&h;
}

// ---------------- kInit ----------------
__global__ void kInit() {
    int t = threadIdx.x;
    if (t < TWOA) { d_s1[t] = 0.0; d_q1[t] = 0.0; }
    if (t < AF)   { d_s2[t] = 0.0; d_q2[t] = 0.0; }
    if (t == 0)   { d_c1 = 0u; d_c2 = 0u; }
}

// ---------------- kA: SW = atom@W1 + b (fp32); PW = atom@W2 packed fp16 -> d_PW16 ----------
__global__ void __launch_bounds__(256) kA(const float* __restrict__ atom,
                                          const float* __restrict__ W,
                                          const float* __restrict__ bias) {
    __shared__ __align__(16) float at[64][132];
    int t = threadIdx.x;
    int aBase = blockIdx.x * 128;
    int aCount = NATOM - aBase; if (aCount > 128) aCount = 128;
    int c = t & 127;                 // column (SW col for t<128, PW col for t>=128)

    float wreg[64];
    const float* wp = (t < 128) ? (W + c) : (W + 64 * TWOA + c);
    #pragma unroll
    for (int k = 0; k < 64; k++) wreg[k] = wp[k * TWOA];
    float bj = (t < 128) ? bias[c] : 0.0f;

    for (int idx = t; idx < 128 * 64; idx += 256) {
        int a = idx >> 6, k = idx & 63;
        at[k][a] = (a < aCount) ? atom[(size_t)(aBase + a) * AF + k] : 0.0f;
    }
    __syncthreads();

    u32* pw32 = (u32*)d_PW16;
    int widx = (c < 64) ? c : (c - 63);   // u32 index within packed PW row (for even c)

    for (int cc = 0; cc < 16; cc++) {
        int a0 = cc * 8;
        ull acc[4] = {0ull, 0ull, 0ull, 0ull};
        #pragma unroll
        for (int k = 0; k < 64; k++) {
            ull wk = packdup(wreg[k]);
            const ull* ap = (const ull*)&at[k][a0];
            ffma2(acc[0], ap[0], wk);
            ffma2(acc[1], ap[1], wk);
            ffma2(acc[2], ap[2], wk);
            ffma2(acc[3], ap[3], wk);
        }
        #pragma unroll
        for (int q = 0; q < 4; q++) {
            float2 v = unpk(acc[q]);
            int a = a0 + 2 * q;
            if (t < 128) {
                if (a < aCount)     d_SW[(size_t)(aBase + a)     * TWOA + c] = v.x + bj;
                if (a + 1 < aCount) d_SW[(size_t)(aBase + a + 1) * TWOA + c] = v.y + bj;
            } else {
                // pack fp16 pairs with the +1 lane (adjacent column, same warp)
                float ox = __shfl_down_sync(0xffffffffu, v.x, 1);
                float oy = __shfl_down_sync(0xffffffffu, v.y, 1);
                if (!(c & 1)) {
                    if (a < aCount)
                        pw32[(size_t)(aBase + a) * 64 + widx] = packh2(v.x, ox);
                    if (a + 1 < aCount)
                        pw32[(size_t)(aBase + a + 1) * 64 + widx] = packh2(v.y, oy);
                }
            }
        }
    }
}

// ============ persistent kGemmStore (R13 proven): 384 thr = 12 warps x 8 rows ============
__global__ void __launch_bounds__(384, 2) kGemmStore(const float* __restrict__ bond,
                                                     const int*   __restrict__ nidx,
                                                     const float* __restrict__ W,
                                                     const float* __restrict__ sc,
                                                     const float* __restrict__ of) {
    extern __shared__ __align__(16) char sm[];
    float* Ws   = (float*)(sm + OFF_WS);
    float* bT   = (float*)(sm + OFF_BT);
    float* braw = (float*)(sm + OFF_BRAW);
    float* SWs  = (float*)(sm + OFF_SWS);
    ull*   PWs  = (ull*)  (sm + OFF_PWS);
    int*   idxS = (int*)  (sm + OFF_IDX);
    __shared__ int sLast;

    int t = threadIdx.x, lane = t & 31, w = t >> 5;
    int r0 = 8 * w;
    int cA = 2 * lane;

    // ---- prolog ----
    {
        int t0 = blockIdx.x;
        int t1 = t0 + PBLOCKS;
        const float* bsrc = bond + (size_t)t0 * 96 * BF;
        #pragma unroll
        for (int i = 0; i < 3; i++) {
            int c = t + 384 * i;
            if (c < 96 * BF / 4) cpasync16(braw + c * 4, bsrc + c * 4);
        }
        if (t < 256) cpasync16(SWs + t * 4, d_SW + (size_t)t0 * 8 * TWOA + t * 4);
        if (t < 24) {
            cpasync16(idxS + t * 4,      nidx + t0 * 96 + t * 4);
            cpasync16(idxS + 96 + t * 4, nidx + t1 * 96 + t * 4);
        }
        CP_COMMIT();
        const float* wsrc = W + TWOA * TWOA;
        #pragma unroll
        for (int i = 0; i < 4; i++) {
            int c = t + 384 * i;
            if (c < BF * TWOA / 4) cpasync16(Ws + c * 4, wsrc + c * 4);
        }
        CP_COMMIT();
        CP_WAIT(0);
        __syncthreads();
        #pragma unroll
        for (int i = 0; i < 4; i++) {
            int id = t + 384 * i;
            int row = id >> 4, ch = id & 15;
            cpasync16((char*)(PWs + row * 32) + ch * 16,
                      (const char*)(d_PW16 + (size_t)idxS[row] * 32) + ch * 16);
        }
        CP_COMMIT();
    }

    float ls0 = 0, ls1 = 0, ls2 = 0, ls3 = 0;
    float lq0 = 0, lq1 = 0, lq2 = 0, lq3 = 0;

    int n = 0;
    for (int tile = blockIdx.x; tile < NT; tile += PBLOCKS, ++n) {
        int nt1 = tile + PBLOCKS;
        bool more = nt1 < NT;

        CP_WAIT(1);
        __syncthreads();

        #pragma unroll
        for (int i = 0; i < 11; i++) {
            int id = t + 384 * i;
            if (id < 96 * BF) {
                int k = id / 96, r = id - 96 * k;
                bT[k * BT_PAD + r] = braw[r * BF + k];
            }
        }
        __syncthreads();

        if (more) {
            const float* bsrc = bond + (size_t)nt1 * 96 * BF;
            #pragma unroll
            for (int i = 0; i < 3; i++) {
                int c = t + 384 * i;
                if (c < 96 * BF / 4) cpasync16(braw + c * 4, bsrc + c * 4);
            }
            if (t < 256) cpasync16(SWs + ((n + 1) & 1) * 1024 + t * 4,
                                   d_SW + (size_t)nt1 * 8 * TWOA + t * 4);
            int nt2 = nt1 + PBLOCKS;
            if (nt2 < NT && t < 24)
                cpasync16(idxS + ((n + 2) % 3) * 96 + t * 4, nidx + nt2 * 96 + t * 4);
            CP_COMMIT();
            const int* idn = idxS + ((n + 1) % 3) * 96;
            ull* pwd = PWs + ((n + 1) & 1) * 3072;
            #pragma unroll
            for (int i = 0; i < 4; i++) {
                int id = t + 384 * i;
                int row = id >> 4, ch = id & 15;
                cpasync16((char*)(pwd + row * 32) + ch * 16,
                          (const char*)(d_PW16 + (size_t)idn[row] * 32) + ch * 16);
            }
            CP_COMMIT();
        }

        ull acc[4][4];
        #pragma unroll
        for (int p = 0; p < 4; p++)
            #pragma unroll
            for (int u = 0; u < 4; u++) acc[p][u] = 0ull;

        #pragma unroll
        for (int k = 0; k < BF; k++) {
            float2 wa = *(const float2*)&Ws[k * TWOA + cA];
            float2 wb = *(const float2*)&Ws[k * TWOA + 64 + cA];
            ull w0 = packdup(wa.x), w1 = packdup(wa.y);
            ull w2 = packdup(wb.x), w3 = packdup(wb.y);
            const char* brow = (const char*)(bT + k * BT_PAD + r0);
            ulonglong2 q0 = *(const ulonglong2*)(brow);
            ulonglong2 q1 = *(const ulonglong2*)(brow + 16);
            ull bv0 = q0.x, bv1 = q0.y, bv2 = q1.x, bv3 = q1.y;
            ffma2(acc[0][0], bv0, w0); ffma2(acc[0][1], bv0, w1); ffma2(acc[0][2], bv0, w2); ffma2(acc[0][3], bv0, w3);
            ffma2(acc[1][0], bv1, w0); ffma2(acc[1][1], bv1, w1); ffma2(acc[1][2], bv1, w2); ffma2(acc[1][3], bv1, w3);
            ffma2(acc[2][0], bv2, w0); ffma2(acc[2][1], bv2, w1); ffma2(acc[2][2], bv2, w2); ffma2(acc[2][3], bv2, w3);
            ffma2(acc[3][0], bv3, w0); ffma2(acc[3][1], bv3, w1); ffma2(acc[3][2], bv3, w2); ffma2(acc[3][3], bv3, w3);
        }

        if (more) { CP_WAIT(2); } else { CP_WAIT(0); }
        __syncthreads();

        const float* SWb = SWs + (n & 1) * 1024;
        const ull*   PWb = PWs + (n & 1) * 3072;
        ull* gbase = d_gated16 + (size_t)(tile * 96 + r0) * 32;

        #pragma unroll
        for (int p = 0; p < 4; p++) {
            float2 aA0 = unpk(acc[p][0]), aA1 = unpk(acc[p][1]);
            float2 aB0 = unpk(acc[p][2]), aB1 = unpk(acc[p][3]);
            #pragma unroll
            for (int s = 0; s < 2; s++) {
                int rr = r0 + 2 * p + s;
                int aLoc = rr / 12;
                const float* swr = SWb + aLoc * TWOA;
                ull pk = PWb[rr * 32 + lane];
                unsigned plo = (unsigned)pk, phi = (unsigned)(pk >> 32);
                float2 pA = __half22float2(*(__half2*)&plo);
                float2 pB = __half22float2(*(__half2*)&phi);
                float2 swA = *(const float2*)(swr + cA);
                float2 swB = *(const float2*)(swr + 64 + cA);
                float v0 = (s ? aA0.y : aA0.x) + swA.x + pA.x;
                float v1 = (s ? aA1.y : aA1.x) + swA.y + pA.y;
                float v2 = (s ? aB0.y : aB0.x) + swB.x + pB.x;
                float v3 = (s ? aB1.y : aB1.x) + swB.y + pB.y;
                __half2 hA = __floats2half2_rn(v0, v1);
                __half2 hB = __floats2half2_rn(v2, v3);
                unsigned uA = *(unsigned*)&hA, uB = *(unsigned*)&hB;
                __stcs(gbase + (size_t)(2 * p + s) * 32 + lane, (ull)uA | ((ull)uB << 32));
                ls0 += v0; lq0 += v0 * v0;
                ls1 += v1; lq1 += v1 * v1;
                ls2 += v2; lq2 += v2 * v2;
                ls3 += v3; lq3 += v3 * v3;
            }
        }
    }

    __syncthreads();
    float* redS = (float*)(sm + OFF_RED);
    float* redQ = redS + 12 * TWOA;
    redS[w * TWOA + cA] = ls0;       redS[w * TWOA + cA + 1] = ls1;
    redS[w * TWOA + 64 + cA] = ls2;  redS[w * TWOA + 64 + cA + 1] = ls3;
    redQ[w * TWOA + cA] = lq0;       redQ[w * TWOA + cA + 1] = lq1;
    redQ[w * TWOA + 64 + cA] = lq2;  redQ[w * TWOA + 64 + cA + 1] = lq3;
    __syncthreads();
    if (t < TWOA) {
        float s = 0.0f, q = 0.0f;
        #pragma unroll
        for (int w2 = 0; w2 < 12; w2++) { s += redS[w2 * TWOA + t]; q += redQ[w2 * TWOA + t]; }
        atomicAdd(&d_s1[t], (double)s);
        atomicAdd(&d_q1[t], (double)q);
    }
    __syncthreads();
    if (t == 0) {
        __threadfence();
        unsigned old = atomicAdd(&d_c1, 1u);
        sLast = (old == PBLOCKS - 1) ? 1 : 0;
    }
    __syncthreads();
    if (sLast && t < TWOA) {
        double s = *((volatile double*)&d_s1[t]);
        double q = *((volatile double*)&d_q1[t]);
        double mean = s / NMF;
        double var  = q / NMF - mean * mean;
        float g = sc[t] * (float)(1.0 / sqrt(var + EPSBN));
        d_g1[t] = g;
        d_h1[t] = of[t] - (float)mean * g;
    }
}

// ---------------- kC: persistent; software-pipelined loads (2-buffer ping-pong) ----------
#define KC_LOAD(buf, a_) { \
    const uint4* gp_ = (const uint4*)(d_gated16 + (size_t)(a_) * MNBR * 32); \
    _Pragma("unroll") \
    for (int i_ = 0; i_ < 6; i_++) buf[i_] = __ldcs(gp_ + (2 * i_ + half) * 16 + q); \
}
#define KC_COMPUTE(buf, a_) { \
    float s0 = 0.0f, s1 = 0.0f, s2 = 0.0f, s3 = 0.0f; \
    _Pragma("unroll") \
    for (int i_ = 0; i_ < 6; i_++) { \
        float2 f01 = __half22float2(*(__half2*)&buf[i_].x); \
        float2 c01 = __half22float2(*(__half2*)&buf[i_].y); \
        float2 f23 = __half22float2(*(__half2*)&buf[i_].z); \
        float2 c23 = __half22float2(*(__half2*)&buf[i_].w); \
        s0 += sigmoidf_(f01.x * G1A.x + H1A.x) * softplusf_(c01.x * G1B.x + H1B.x); \
        s1 += sigmoidf_(f01.y * G1A.y + H1A.y) * softplusf_(c01.y * G1B.y + H1B.y); \
        s2 += sigmoidf_(f23.x * G1A.z + H1A.z) * softplusf_(c23.x * G1B.z + H1B.z); \
        s3 += sigmoidf_(f23.y * G1A.w + H1A.w) * softplusf_(c23.y * G1B.w + H1B.w); \
    } \
    s0 += __shfl_xor_sync(0xffffffffu, s0, 16); \
    s1 += __shfl_xor_sync(0xffffffffu, s1, 16); \
    s2 += __shfl_xor_sync(0xffffffffu, s2, 16); \
    s3 += __shfl_xor_sync(0xffffffffu, s3, 16); \
    if (half == 0) { \
        float4 sv; sv.x = s0; sv.y = s1; sv.z = s2; sv.w = s3; \
        *(float4*)&d_summed[(size_t)(a_) * AF + c0] = sv; \
        as0 += s0; aq0 += s0 * s0; \
        as1 += s1; aq1 += s1 * s1; \
        as2 += s2; aq2 += s2 * s2; \
        as3 += s3; aq3 += s3 * s3; \
    } \
}

__global__ void __launch_bounds__(256, 3) kC(const float* __restrict__ sc,
                                             const float* __restrict__ of) {
    __shared__ float rs[8][AF];
    __shared__ float rq[8][AF];
    __shared__ int sLast;
    int t = threadIdx.x;
    int lane = t & 31, w = t >> 5;
    int half = lane >> 4, q = lane & 15;
    int c0 = 4 * q;

    float4 G1A = *(const float4*)&d_g1[c0];
    float4 H1A = *(const float4*)&d_h1[c0];
    float4 G1B = *(const float4*)&d_g1[64 + c0];
    float4 H1B = *(const float4*)&d_h1[64 + c0];

    float as0 = 0, as1 = 0, as2 = 0, as3 = 0;
    float aq0 = 0, aq1 = 0, aq2 = 0, aq3 = 0;

    for (int tb = blockIdx.x; tb < NTC; tb += PB_C) {
        int aBase = tb * 32 + w * 4;
        uint4 va[6], vb[6];
        KC_LOAD(va, aBase)
        KC_LOAD(vb, aBase + 1)          // both in flight
        KC_COMPUTE(va, aBase)
        KC_LOAD(va, aBase + 2)
        KC_COMPUTE(vb, aBase + 1)
        KC_LOAD(vb, aBase + 3)
        KC_COMPUTE(va, aBase + 2)
        KC_COMPUTE(vb, aBase + 3)
    }

    if (half == 0) {
        float4 sv; sv.x = as0; sv.y = as1; sv.z = as2; sv.w = as3;
        *(float4*)&rs[w][c0] = sv;
        float4 qv; qv.x = aq0; qv.y = aq1; qv.z = aq2; qv.w = aq3;
        *(float4*)&rq[w][c0] = qv;
    }
    __syncthreads();
    if (t < AF) {
        float s = 0.0f, qq = 0.0f;
        #pragma unroll
        for (int r = 0; r < 8; r++) { s += rs[r][t]; qq += rq[r][t]; }
        atomicAdd(&d_s2[t], (double)s);
        atomicAdd(&d_q2[t], (double)qq);
    }
    __syncthreads();
    if (t == 0) {
        __threadfence();
        unsigned old = atomicAdd(&d_c2, 1u);
        sLast = (old == PB_C - 1) ? 1 : 0;
    }
    __syncthreads();
    if (sLast && t < AF) {
        double s = *((volatile double*)&d_s2[t]);
        double qq = *((volatile double*)&d_q2[t]);
        double mean = s / NF;
        double var  = qq / NF - mean * mean;
        float g = sc[t] * (float)(1.0 / sqrt(var + EPSBN));
        d_g2[t] = g;
        d_h2[t] = of[t] - (float)mean * g;
    }
}

// ---------------- kD: out = softplus(atom + BN2(summed)) ----------------
__global__ void __launch_bounds__(256) kD(const float* __restrict__ atom,
                                          float* __restrict__ out) {
    int i = blockIdx.x * 256 + threadIdx.x;
    int c = i & (AF - 1);
    float y = d_summed[i] * d_g2[c] + d_h2[c];
    out[i] = softplusf_(atom[i] + y);
}

// ---------------- launch ----------------
extern "C" void kernel_launch(void* const* d_in, const int* in_sizes, int n_in,
                              void* d_out, int out_size) {
    const int*   nidx = (const int*)  d_in[0];
    const float* atom = (const float*)d_in[1];
    const float* bond = (const float*)d_in[2];
    const float* W    = (const float*)d_in[3];
    const float* bias = (const float*)d_in[4];
    const float* bn1s = (const float*)d_in[5];
    const float* bn1o = (const float*)d_in[6];
    const float* bn2s = (const float*)d_in[7];
    const float* bn2o = (const float*)d_in[8];
    float* out = (float*)d_out;

    cudaFuncSetAttribute(kGemmStore, cudaFuncAttributeMaxDynamicSharedMemorySize, SMEM_BYTES);

    kInit<<<1, 128>>>();                                                     // slot 1
    kA<<<(NATOM + 127) / 128, 256>>>(atom, W, bias);                         // slot 2 (now packs PW16)
    kGemmStore<<<PBLOCKS, 384, SMEM_BYTES>>>(bond, nidx, W, bn1s, bn1o);     // slot 3
    kC<<<PB_C, 256>>>(bn2s, bn2o);                                           // slot 4 (ncu)
    kD<<<(NATOM * AF) / 256, 256>>>(atom, out);                              // slot 5
}